// round 12
// baseline (speedup 1.0000x reference)
#include <cuda_runtime.h>
#include <cuda_bf16.h>
#include <cstdint>

// ---------------- problem constants ----------------
#define BB 16
#define QQ 100
#define TT 50
#define GG 16384
#define LL 21
#define KSPLIT 9                 // grid = 16*9 = 144 CTAs (~1 wave)
#define KC 64                    // K per stage (64 bf16 = 128B row)
#define NTHREADS 512

// per-stage smem tile offsets (bytes)
#define OFF_AM 0                 // 128 rows x 128B bf16 (mask logits)
#define OFF_AS 16384             // 128 rows x 128B bf16 (sigmoid)
#define OFF_Y  32768             // 64 rows x 128B bf16 (targets)
#define STAGE_BYTES 40960
#define SMEM_DYN (2 * STAGE_BYTES)   // 81920

// ---------------- device scratch: per-ks slices, fully overwritten ----------------
__device__ float g_Dm[KSPLIT * BB * QQ * TT];
__device__ float g_Ds[KSPLIT * BB * QQ * TT];
__device__ float g_Ssp[KSPLIT * BB * QQ];
__device__ float g_Ssg[KSPLIT * BB * QQ];
__device__ float g_Sy[KSPLIT * BB * TT];

// ---------------- helpers ----------------
__device__ __forceinline__ uint32_t smem_u32(const void* p) {
    uint32_t a;
    asm("{ .reg .u64 t; cvta.to.shared.u64 t, %1; cvt.u32.u64 %0, t; }"
        : "=r"(a) : "l"(p));
    return a;
}
// softplus + sigmoid with 2 MUFU: tanh + lg2
__device__ __forceinline__ void act(float v, float& sp, float& sg) {
    float h;
    asm("tanh.approx.f32 %0, %1;" : "=f"(h) : "f"(0.5f * v));
    float sgn = fmaf(-0.5f, h, 0.5f);
    sg = fmaf(0.5f, h, 0.5f);
    sgn = fmaxf(sgn, 1e-30f);
    float lg;
    asm("lg2.approx.f32 %0, %1;" : "=f"(lg) : "f"(sgn));
    sp = -0.6931471805599453f * lg;
}
__device__ __forceinline__ float redWarp(float v) {
#pragma unroll
    for (int o = 16; o; o >>= 1) v += __shfl_xor_sync(0xFFFFFFFFu, v, o);
    return v;
}
#define LDSM4(r, addr)                                                        \
    asm volatile("ldmatrix.sync.aligned.m8n8.x4.shared.b16 {%0,%1,%2,%3}, [%4];" \
                 : "=r"((r)[0]), "=r"((r)[1]), "=r"((r)[2]), "=r"((r)[3])     \
                 : "r"(addr))

// ---------------- main: activations + split-K HMMA GEMMs ----------------
__global__ void __launch_bounds__(NTHREADS, 1)
matcher_main(const float* __restrict__ m, const float* __restrict__ y) {
    extern __shared__ char smem[];
    uint32_t sb = smem_u32(smem);
    int tid = threadIdx.x;
    int wid = tid >> 5;
    int lane = tid & 31;
    int b = blockIdx.x / KSPLIT;
    int ks = blockIdx.x % KSPLIT;
    int nst = 28 + (ks < 4 ? 1 : 0);
    int s0 = 28 * ks + (ks < 4 ? ks : 4);
    int g0 = s0 * KC;

    // zero both stage buffers once (pad rows A[100:128), Y[50:64) must stay 0)
    {
        uint4 z = make_uint4(0u, 0u, 0u, 0u);
        for (int i = tid; i < SMEM_DYN / 16; i += NTHREADS)
            reinterpret_cast<uint4*>(smem)[i] = z;
    }
    __syncthreads();

    const bool isFill = (wid >= 8);
    const int fw = wid - 8;             // 0..7 for fillers

    // ---------------- filler state ----------------
    float spA[13], sgA[13], syA[7];
#pragma unroll
    for (int j = 0; j < 13; ++j) { spA[j] = 0.0f; sgA[j] = 0.0f; }
#pragma unroll
    for (int j = 0; j < 7; ++j) syA[j] = 0.0f;

    const float* mBase = m + (size_t)b * QQ * GG + g0 + lane * 2;
    const float* yBase = y + (size_t)b * TT * GG + g0 + lane * 2;
    uint32_t stsOffBase = (uint32_t)((lane * 4));

    auto fillStage = [&](int it, int buf) {
        char* stg = smem + buf * STAGE_BYTES;
        int gk = it * KC;
#pragma unroll
        for (int j = 0; j < 13; ++j) {
            int row = fw + 8 * j;
            if (row < QQ) {
                float2 v = *(const float2*)(mBase + (size_t)row * GG + gk);
                float sa, ga, sc, gc;
                act(v.x, sa, ga);
                act(v.y, sc, gc);
                spA[j] += sa + sc;
                sgA[j] += ga + gc;
                uint32_t off = (uint32_t)(row * 128) +
                               (stsOffBase ^ (uint32_t)((row & 7) << 4));
                __nv_bfloat162 hm = __floats2bfloat162_rn(v.x, v.y);
                __nv_bfloat162 hs = __floats2bfloat162_rn(ga, gc);
                *(uint32_t*)(stg + OFF_AM + off) = *reinterpret_cast<uint32_t*>(&hm);
                *(uint32_t*)(stg + OFF_AS + off) = *reinterpret_cast<uint32_t*>(&hs);
            }
        }
#pragma unroll
        for (int j = 0; j < 7; ++j) {
            int row = fw + 8 * j;
            if (row < TT) {
                float2 v = *(const float2*)(yBase + (size_t)row * GG + gk);
                syA[j] += v.x + v.y;
                uint32_t off = (uint32_t)(row * 128) +
                               (stsOffBase ^ (uint32_t)((row & 7) << 4));
                __nv_bfloat162 hv = __floats2bfloat162_rn(v.x, v.y);
                *(uint32_t*)(stg + OFF_Y + off) = *reinterpret_cast<uint32_t*>(&hv);
            }
        }
    };

    // ---------------- consumer state (wid 0..7 = strip) ----------------
    const int mt = wid;                 // strip (rows mt*16 .. +16)
    const int gq = lane >> 2;           // 0..7
    const int tig = lane & 3;           // 0..3
    float accM[7][4], accS[7][4];
#pragma unroll
    for (int nt = 0; nt < 7; ++nt)
#pragma unroll
        for (int i = 0; i < 4; ++i) { accM[nt][i] = 0.0f; accS[nt][i] = 0.0f; }

    // ldmatrix lane address terms (loop-invariant)
    uint32_t cmask = (uint32_t)((lane & 7) << 4);
    uint32_t rowA = (uint32_t)(mt * 16 + (lane & 15));
    uint32_t rowAoff = rowA * 128;
    uint32_t chintA = (lane & 16) ? 16u : 0u;
    uint32_t chintB = (lane & 8) ? 16u : 0u;
    uint32_t rbB[4];
#pragma unroll
    for (int i = 0; i < 4; ++i) {
        uint32_t tB = (uint32_t)(16 * i + (lane & 7) + ((lane & 16) ? 8 : 0));
        rbB[i] = tB * 128;
    }

    auto mmaStage = [&](int buf) {
        uint32_t base = sb + (uint32_t)(buf * STAGE_BYTES);
        uint32_t amb = base + OFF_AM + rowAoff;
        uint32_t asb = base + OFF_AS + rowAoff;
        uint32_t ybv = base + OFF_Y;
#pragma unroll
        for (int kc = 0; kc < 4; ++kc) {
            uint32_t cb16 = (uint32_t)(kc * 32);
            uint32_t ccA = (cb16 + chintA) ^ cmask;
            uint32_t ccB = (cb16 + chintB) ^ cmask;
            uint32_t am[4], as4[4], bb[4][4];
            LDSM4(am, amb + ccA);
            LDSM4(as4, asb + ccA);
#pragma unroll
            for (int i = 0; i < 4; ++i) LDSM4(bb[i], ybv + rbB[i] + ccB);
#pragma unroll
            for (int nt = 0; nt < 7; ++nt) {
                uint32_t b0 = bb[nt >> 1][(nt & 1) * 2];
                uint32_t b1 = bb[nt >> 1][(nt & 1) * 2 + 1];
                asm volatile(
                    "mma.sync.aligned.m16n8k16.row.col.f32.bf16.bf16.f32 "
                    "{%0,%1,%2,%3}, {%4,%5,%6,%7}, {%8,%9}, {%0,%1,%2,%3};"
                    : "+f"(accM[nt][0]), "+f"(accM[nt][1]),
                      "+f"(accM[nt][2]), "+f"(accM[nt][3])
                    : "r"(am[0]), "r"(am[1]), "r"(am[2]), "r"(am[3]),
                      "r"(b0), "r"(b1));
                asm volatile(
                    "mma.sync.aligned.m16n8k16.row.col.f32.bf16.bf16.f32 "
                    "{%0,%1,%2,%3}, {%4,%5,%6,%7}, {%8,%9}, {%0,%1,%2,%3};"
                    : "+f"(accS[nt][0]), "+f"(accS[nt][1]),
                      "+f"(accS[nt][2]), "+f"(accS[nt][3])
                    : "r"(as4[0]), "r"(as4[1]), "r"(as4[2]), "r"(as4[3]),
                      "r"(b0), "r"(b1));
            }
        }
    };

    // ---------------- pipeline ----------------
    if (isFill) fillStage(0, 0);
    __syncthreads();
#pragma unroll 1
    for (int it = 0; it < nst; ++it) {
        if (isFill) {
            if (it + 1 < nst) fillStage(it + 1, (it + 1) & 1);
        } else {
            mmaStage(it & 1);
        }
        __syncthreads();
    }

    int sl = ks * BB + b;

    // ---- row-sum reductions (fillers; one-time) ----
    if (isFill) {
#pragma unroll
        for (int j = 0; j < 13; ++j) {
            int row = fw + 8 * j;
            if (row < QQ) {
                float s1 = redWarp(spA[j]);
                float s2 = redWarp(sgA[j]);
                if (lane == 0) {
                    g_Ssp[sl * QQ + row] = s1;
                    g_Ssg[sl * QQ + row] = s2;
                }
            }
        }
#pragma unroll
        for (int j = 0; j < 7; ++j) {
            int row = fw + 8 * j;
            if (row < TT) {
                float s3 = redWarp(syA[j]);
                if (lane == 0) g_Sy[sl * TT + row] = s3;
            }
        }
    } else {
        // ---- D slice stores (unique writer per entry, no atomics) ----
        int rl = mt * 16 + gq;
        int rh = rl + 8;
        size_t sbase = (size_t)sl * QQ * TT;
#pragma unroll
        for (int nt = 0; nt < 7; ++nt) {
            int ca = nt * 8 + tig * 2;
            int cb2 = ca + 1;
            if (rl < QQ) {
                if (ca < TT) {
                    g_Dm[sbase + rl * TT + ca] = accM[nt][0];
                    g_Ds[sbase + rl * TT + ca] = accS[nt][0];
                }
                if (cb2 < TT) {
                    g_Dm[sbase + rl * TT + cb2] = accM[nt][1];
                    g_Ds[sbase + rl * TT + cb2] = accS[nt][1];
                }
            }
            if (rh < QQ) {
                if (ca < TT) {
                    g_Dm[sbase + rh * TT + ca] = accM[nt][2];
                    g_Ds[sbase + rh * TT + ca] = accS[nt][2];
                }
                if (cb2 < TT) {
                    g_Dm[sbase + rh * TT + cb2] = accM[nt][3];
                    g_Ds[sbase + rh * TT + cb2] = accS[nt][3];
                }
            }
        }
    }
}

// ---------------- epilogue: one warp per (b,q) ----------------
__global__ void __launch_bounds__(128, 8)
matcher_epi(const float* __restrict__ cl,
            const int* __restrict__ lab32,
            float* __restrict__ out) {
    int warp = (blockIdx.x * blockDim.x + threadIdx.x) >> 5;
    int lane = threadIdx.x & 31;
    if (warp >= BB * QQ) return;
    int b = warp / QQ;
    int q = warp - b * QQ;

    // int64-vs-int32 label detection (warp-uniform)
    int i64;
    {
        int ok = 1;
#pragma unroll
        for (int k = 0; k < 8; ++k) {
            int lo = lab32[2 * k], hi = lab32[2 * k + 1];
            if (hi != 0 || lo < 0 || lo >= LL) { ok = 0; break; }
        }
        i64 = ok;
    }

    // lane-parallel softmax over L=21
    const float* c = cl + (size_t)(b * QQ + q) * LL;
    float v = (lane < LL) ? c[lane] : -1e30f;
    float mx = v;
#pragma unroll
    for (int o = 16; o; o >>= 1) mx = fmaxf(mx, __shfl_xor_sync(0xFFFFFFFFu, mx, o));
    float e = (lane < LL) ? __expf(v - mx) : 0.0f;
    float s = e;
#pragma unroll
    for (int o = 16; o; o >>= 1) s += __shfl_xor_sync(0xFFFFFFFFu, s, o);
    float pl = e / s;

    float ssp = 0.0f, ssg = 0.0f;
#pragma unroll
    for (int ks = 0; ks < KSPLIT; ++ks) {
        int sl = ks * BB + b;
        ssp += g_Ssp[sl * QQ + q];
        ssg += g_Ssg[sl * QQ + q];
    }

    const float invG = 1.0f / (float)GG;
    size_t rowoff = (size_t)(b * QQ + q) * TT;

#pragma unroll
    for (int half = 0; half < 2; ++half) {
        int t = lane + half * 32;
        if (t < TT) {
            float dm = 0.0f, ds = 0.0f, sy = 0.0f;
#pragma unroll
            for (int ks = 0; ks < KSPLIT; ++ks) {
                int sl = ks * BB + b;
                size_t off = (size_t)sl * QQ * TT + q * TT + t;
                dm += g_Dm[off];
                ds += g_Ds[off];
                sy += g_Sy[sl * TT + t];
            }
            int idx = b * TT + t;
            int lbl = i64 ? lab32[2 * idx] : lab32[idx];
            float p = __shfl_sync(0xFFFFFFFFu, pl, lbl);
            float dice = 1.0f - (2.0f * ds + 1.0f) / (ssg + sy + 1.0f);
            out[rowoff + t] = (ssp - dm) * invG - p + dice;
        } else {
            __shfl_sync(0xFFFFFFFFu, pl, 0);
        }
    }
}

// ---------------- launch ----------------
extern "C" void kernel_launch(void* const* d_in, const int* in_sizes, int n_in,
                              void* d_out, int out_size) {
    (void)in_sizes; (void)n_in; (void)out_size;
    const float* m = (const float*)d_in[0];
    const float* cl = (const float*)d_in[1];
    const float* y = (const float*)d_in[2];
    const int* lab = (const int*)d_in[3];
    float* out = (float*)d_out;

    cudaFuncSetAttribute(matcher_main,
                         cudaFuncAttributeMaxDynamicSharedMemorySize, SMEM_DYN);

    matcher_main<<<BB * KSPLIT, NTHREADS, SMEM_DYN>>>(m, y);
    matcher_epi<<<(BB * QQ + 3) / 4, 128>>>(cl, lab, out);
}

// round 13
// speedup vs baseline: 1.5287x; 1.5287x over previous
#include <cuda_runtime.h>
#include <cuda_bf16.h>
#include <cstdint>

// ---------------- problem constants ----------------
#define BB 16
#define QQ 100
#define TT 50
#define GG 16384
#define LL 21
#define KSPLIT 9                 // grid = 16*9 = 144 CTAs (~1 wave)
#define KC 64                    // K per stage (64 bf16 = 128B row)
#define NTHREADS 512

// per-stage smem tile offsets (bytes)
#define OFF_AM 0                 // 128 rows x 128B bf16 (mask logits)
#define OFF_AS 16384             // 128 rows x 128B bf16 (sigmoid)
#define OFF_Y  32768             // 64 rows x 128B bf16 (targets)
#define STAGE_BYTES 40960
#define SMEM_DYN (2 * STAGE_BYTES)   // 81920

// ---------------- device scratch: per-ks slices, fully overwritten ----------------
__device__ float g_Dm[KSPLIT * BB * QQ * TT];
__device__ float g_Ds[KSPLIT * BB * QQ * TT];
__device__ float g_Ssp[KSPLIT * BB * QQ];
__device__ float g_Ssg[KSPLIT * BB * QQ];
__device__ float g_Sy[KSPLIT * BB * TT];

// ---------------- helpers ----------------
__device__ __forceinline__ uint32_t smem_u32(const void* p) {
    uint32_t a;
    asm("{ .reg .u64 t; cvta.to.shared.u64 t, %1; cvt.u32.u64 %0, t; }"
        : "=r"(a) : "l"(p));
    return a;
}
// softplus + sigmoid with 2 MUFU: tanh + lg2
__device__ __forceinline__ void act(float v, float& sp, float& sg) {
    float h;
    asm("tanh.approx.f32 %0, %1;" : "=f"(h) : "f"(0.5f * v));
    float sgn = fmaf(-0.5f, h, 0.5f);
    sg = fmaf(0.5f, h, 0.5f);
    sgn = fmaxf(sgn, 1e-30f);
    float lg;
    asm("lg2.approx.f32 %0, %1;" : "=f"(lg) : "f"(sgn));
    sp = -0.6931471805599453f * lg;
}
__device__ __forceinline__ float redWarp(float v) {
#pragma unroll
    for (int o = 16; o; o >>= 1) v += __shfl_xor_sync(0xFFFFFFFFu, v, o);
    return v;
}
#define LDSM4(r, addr)                                                        \
    asm volatile("ldmatrix.sync.aligned.m8n8.x4.shared.b16 {%0,%1,%2,%3}, [%4];" \
                 : "=r"((r)[0]), "=r"((r)[1]), "=r"((r)[2]), "=r"((r)[3])     \
                 : "r"(addr))

// ---------------- main: activations + split-K HMMA GEMMs ----------------
__global__ void __launch_bounds__(NTHREADS, 1)
matcher_main(const float* __restrict__ m, const float* __restrict__ y) {
    extern __shared__ char smem[];
    uint32_t sb = smem_u32(smem);
    int tid = threadIdx.x;
    int wid = tid >> 5;
    int lane = tid & 31;
    int b = blockIdx.x / KSPLIT;
    int ks = blockIdx.x % KSPLIT;
    int nst = 28 + (ks < 4 ? 1 : 0);
    int s0 = 28 * ks + (ks < 4 ? ks : 4);
    int g0 = s0 * KC;

    // zero both stage buffers once (pad rows A[100:128), Y[50:64) must stay 0)
    {
        uint4 z = make_uint4(0u, 0u, 0u, 0u);
        for (int i = tid; i < SMEM_DYN / 16; i += NTHREADS)
            reinterpret_cast<uint4*>(smem)[i] = z;
    }
    __syncthreads();

    const bool isFill = (wid >= 8);
    const int fw = wid - 8;             // 0..7 for fillers

    // ---------------- filler state ----------------
    float spA[13], sgA[13], syA[7];
#pragma unroll
    for (int j = 0; j < 13; ++j) { spA[j] = 0.0f; sgA[j] = 0.0f; }
#pragma unroll
    for (int j = 0; j < 7; ++j) syA[j] = 0.0f;

    const float* mBase = m + (size_t)b * QQ * GG + g0 + lane * 2;
    const float* yBase = y + (size_t)b * TT * GG + g0 + lane * 2;
    uint32_t stsOffBase = (uint32_t)(lane * 4);

    float2 vm[13], vy[7];

    // phase 1: issue ALL loads (MLP ~20, hides DRAM latency)
    auto loadStage = [&](int it) {
        int gk = it * KC;
#pragma unroll
        for (int j = 0; j < 13; ++j) {
            int row = fw + 8 * j;
            if (row < QQ) vm[j] = *(const float2*)(mBase + (size_t)row * GG + gk);
        }
#pragma unroll
        for (int j = 0; j < 7; ++j) {
            int row = fw + 8 * j;
            if (row < TT) vy[j] = *(const float2*)(yBase + (size_t)row * GG + gk);
        }
    };

    // phase 2: activations + swizzled STS
    auto storeStage = [&](int buf) {
        char* stg = smem + buf * STAGE_BYTES;
#pragma unroll
        for (int j = 0; j < 13; ++j) {
            int row = fw + 8 * j;
            if (row < QQ) {
                float sa, ga, sc, gc;
                act(vm[j].x, sa, ga);
                act(vm[j].y, sc, gc);
                spA[j] += sa + sc;
                sgA[j] += ga + gc;
                uint32_t off = (uint32_t)(row * 128) +
                               (stsOffBase ^ (uint32_t)((row & 7) << 4));
                __nv_bfloat162 hm = __floats2bfloat162_rn(vm[j].x, vm[j].y);
                __nv_bfloat162 hs = __floats2bfloat162_rn(ga, gc);
                *(uint32_t*)(stg + OFF_AM + off) = *reinterpret_cast<uint32_t*>(&hm);
                *(uint32_t*)(stg + OFF_AS + off) = *reinterpret_cast<uint32_t*>(&hs);
            }
        }
#pragma unroll
        for (int j = 0; j < 7; ++j) {
            int row = fw + 8 * j;
            if (row < TT) {
                syA[j] += vy[j].x + vy[j].y;
                uint32_t off = (uint32_t)(row * 128) +
                               (stsOffBase ^ (uint32_t)((row & 7) << 4));
                __nv_bfloat162 hv = __floats2bfloat162_rn(vy[j].x, vy[j].y);
                *(uint32_t*)(stg + OFF_Y + off) = *reinterpret_cast<uint32_t*>(&hv);
            }
        }
    };

    // ---------------- consumer state (wid 0..7 = strip) ----------------
    const int mt = wid;                 // strip (rows mt*16 .. +16)
    const int gq = lane >> 2;           // 0..7
    const int tig = lane & 3;           // 0..3
    float accM[7][4], accS[7][4];
#pragma unroll
    for (int nt = 0; nt < 7; ++nt)
#pragma unroll
        for (int i = 0; i < 4; ++i) { accM[nt][i] = 0.0f; accS[nt][i] = 0.0f; }

    // ldmatrix lane address terms (loop-invariant)
    uint32_t cmask = (uint32_t)((lane & 7) << 4);
    uint32_t rowA = (uint32_t)(mt * 16 + (lane & 15));
    uint32_t rowAoff = rowA * 128;
    uint32_t chintA = (lane & 16) ? 16u : 0u;
    uint32_t chintB = (lane & 8) ? 16u : 0u;
    uint32_t rbB[4];
#pragma unroll
    for (int i = 0; i < 4; ++i) {
        uint32_t tB = (uint32_t)(16 * i + (lane & 7) + ((lane & 16) ? 8 : 0));
        rbB[i] = tB * 128;
    }

    auto mmaStage = [&](int buf) {
        uint32_t base = sb + (uint32_t)(buf * STAGE_BYTES);
        uint32_t amb = base + OFF_AM + rowAoff;
        uint32_t asb = base + OFF_AS + rowAoff;
        uint32_t ybv = base + OFF_Y;
#pragma unroll
        for (int kc = 0; kc < 4; ++kc) {
            uint32_t cb16 = (uint32_t)(kc * 32);
            uint32_t ccA = (cb16 + chintA) ^ cmask;
            uint32_t ccB = (cb16 + chintB) ^ cmask;
            uint32_t am[4], as4[4], bb[4][4];
            LDSM4(am, amb + ccA);
            LDSM4(as4, asb + ccA);
#pragma unroll
            for (int i = 0; i < 4; ++i) LDSM4(bb[i], ybv + rbB[i] + ccB);
#pragma unroll
            for (int nt = 0; nt < 7; ++nt) {
                uint32_t b0 = bb[nt >> 1][(nt & 1) * 2];
                uint32_t b1 = bb[nt >> 1][(nt & 1) * 2 + 1];
                asm volatile(
                    "mma.sync.aligned.m16n8k16.row.col.f32.bf16.bf16.f32 "
                    "{%0,%1,%2,%3}, {%4,%5,%6,%7}, {%8,%9}, {%0,%1,%2,%3};"
                    : "+f"(accM[nt][0]), "+f"(accM[nt][1]),
                      "+f"(accM[nt][2]), "+f"(accM[nt][3])
                    : "r"(am[0]), "r"(am[1]), "r"(am[2]), "r"(am[3]),
                      "r"(b0), "r"(b1));
                asm volatile(
                    "mma.sync.aligned.m16n8k16.row.col.f32.bf16.bf16.f32 "
                    "{%0,%1,%2,%3}, {%4,%5,%6,%7}, {%8,%9}, {%0,%1,%2,%3};"
                    : "+f"(accS[nt][0]), "+f"(accS[nt][1]),
                      "+f"(accS[nt][2]), "+f"(accS[nt][3])
                    : "r"(as4[0]), "r"(as4[1]), "r"(as4[2]), "r"(as4[3]),
                      "r"(b0), "r"(b1));
            }
        }
    };

    // ---------------- pipeline ----------------
    if (isFill) {
        loadStage(0);
        storeStage(0);
    }
    __syncthreads();
#pragma unroll 1
    for (int it = 0; it < nst; ++it) {
        if (isFill) {
            if (it + 1 < nst) {
                loadStage(it + 1);
                storeStage((it + 1) & 1);
            }
        } else {
            mmaStage(it & 1);
        }
        __syncthreads();
    }

    int sl = ks * BB + b;

    // ---- row-sum reductions (fillers; one-time) ----
    if (isFill) {
#pragma unroll
        for (int j = 0; j < 13; ++j) {
            int row = fw + 8 * j;
            if (row < QQ) {
                float s1 = redWarp(spA[j]);
                float s2 = redWarp(sgA[j]);
                if (lane == 0) {
                    g_Ssp[sl * QQ + row] = s1;
                    g_Ssg[sl * QQ + row] = s2;
                }
            }
        }
#pragma unroll
        for (int j = 0; j < 7; ++j) {
            int row = fw + 8 * j;
            if (row < TT) {
                float s3 = redWarp(syA[j]);
                if (lane == 0) g_Sy[sl * TT + row] = s3;
            }
        }
    } else {
        // ---- D slice stores (unique writer per entry, no atomics) ----
        int rl = mt * 16 + gq;
        int rh = rl + 8;
        size_t sbase = (size_t)sl * QQ * TT;
#pragma unroll
        for (int nt = 0; nt < 7; ++nt) {
            int ca = nt * 8 + tig * 2;
            int cb2 = ca + 1;
            if (rl < QQ) {
                if (ca < TT) {
                    g_Dm[sbase + rl * TT + ca] = accM[nt][0];
                    g_Ds[sbase + rl * TT + ca] = accS[nt][0];
                }
                if (cb2 < TT) {
                    g_Dm[sbase + rl * TT + cb2] = accM[nt][1];
                    g_Ds[sbase + rl * TT + cb2] = accS[nt][1];
                }
            }
            if (rh < QQ) {
                if (ca < TT) {
                    g_Dm[sbase + rh * TT + ca] = accM[nt][2];
                    g_Ds[sbase + rh * TT + ca] = accS[nt][2];
                }
                if (cb2 < TT) {
                    g_Dm[sbase + rh * TT + cb2] = accM[nt][3];
                    g_Ds[sbase + rh * TT + cb2] = accS[nt][3];
                }
            }
        }
    }
}

// ---------------- epilogue: one warp per (b,q) ----------------
__global__ void __launch_bounds__(128, 8)
matcher_epi(const float* __restrict__ cl,
            const int* __restrict__ lab32,
            float* __restrict__ out) {
    int warp = (blockIdx.x * blockDim.x + threadIdx.x) >> 5;
    int lane = threadIdx.x & 31;
    if (warp >= BB * QQ) return;
    int b = warp / QQ;
    int q = warp - b * QQ;

    // int64-vs-int32 label detection (warp-uniform)
    int i64;
    {
        int ok = 1;
#pragma unroll
        for (int k = 0; k < 8; ++k) {
            int lo = lab32[2 * k], hi = lab32[2 * k + 1];
            if (hi != 0 || lo < 0 || lo >= LL) { ok = 0; break; }
        }
        i64 = ok;
    }

    // lane-parallel softmax over L=21
    const float* c = cl + (size_t)(b * QQ + q) * LL;
    float v = (lane < LL) ? c[lane] : -1e30f;
    float mx = v;
#pragma unroll
    for (int o = 16; o; o >>= 1) mx = fmaxf(mx, __shfl_xor_sync(0xFFFFFFFFu, mx, o));
    float e = (lane < LL) ? __expf(v - mx) : 0.0f;
    float s = e;
#pragma unroll
    for (int o = 16; o; o >>= 1) s += __shfl_xor_sync(0xFFFFFFFFu, s, o);
    float pl = e / s;

    float ssp = 0.0f, ssg = 0.0f;
#pragma unroll
    for (int ks = 0; ks < KSPLIT; ++ks) {
        int sl = ks * BB + b;
        ssp += g_Ssp[sl * QQ + q];
        ssg += g_Ssg[sl * QQ + q];
    }

    const float invG = 1.0f / (float)GG;
    size_t rowoff = (size_t)(b * QQ + q) * TT;

#pragma unroll
    for (int half = 0; half < 2; ++half) {
        int t = lane + half * 32;
        if (t < TT) {
            float dm = 0.0f, ds = 0.0f, sy = 0.0f;
#pragma unroll
            for (int ks = 0; ks < KSPLIT; ++ks) {
                int sl = ks * BB + b;
                size_t off = (size_t)sl * QQ * TT + q * TT + t;
                dm += g_Dm[off];
                ds += g_Ds[off];
                sy += g_Sy[sl * TT + t];
            }
            int idx = b * TT + t;
            int lbl = i64 ? lab32[2 * idx] : lab32[idx];
            float p = __shfl_sync(0xFFFFFFFFu, pl, lbl);
            float dice = 1.0f - (2.0f * ds + 1.0f) / (ssg + sy + 1.0f);
            out[rowoff + t] = (ssp - dm) * invG - p + dice;
        } else {
            __shfl_sync(0xFFFFFFFFu, pl, 0);
        }
    }
}

// ---------------- launch ----------------
extern "C" void kernel_launch(void* const* d_in, const int* in_sizes, int n_in,
                              void* d_out, int out_size) {
    (void)in_sizes; (void)n_in; (void)out_size;
    const float* m = (const float*)d_in[0];
    const float* cl = (const float*)d_in[1];
    const float* y = (const float*)d_in[2];
    const int* lab = (const int*)d_in[3];
    float* out = (float*)d_out;

    cudaFuncSetAttribute(matcher_main,
                         cudaFuncAttributeMaxDynamicSharedMemorySize, SMEM_DYN);

    matcher_main<<<BB * KSPLIT, NTHREADS, SMEM_DYN>>>(m, y);
    matcher_epi<<<(BB * QQ + 3) / 4, 128>>>(cl, lab, out);
}

// round 14
// speedup vs baseline: 1.6243x; 1.0625x over previous
#include <cuda_runtime.h>
#include <cuda_bf16.h>
#include <cstdint>

// ---------------- problem constants ----------------
#define BB 16
#define QQ 100
#define TT 50
#define GG 16384
#define LL 21
#define KSPLIT 9                 // grid = 16*9 = 144 CTAs (~1 wave)
#define KC 64                    // K per unit (64 bf16 = 128B row)
#define NTHREADS 512
#define NBUF 4

// per-unit smem tile offsets (bytes)
#define OFF_AM 0                 // 128 rows x 128B bf16 (mask logits)
#define OFF_AS 16384             // 128 rows x 128B bf16 (sigmoid)
#define OFF_Y  32768             // 64 rows x 128B bf16 (targets)
#define STAGE_BYTES 40960
#define SMEM_DYN (NBUF * STAGE_BYTES)   // 163840

// ---------------- device scratch: per-ks slices, fully overwritten ----------------
__device__ float g_Dm[KSPLIT * BB * QQ * TT];
__device__ float g_Ds[KSPLIT * BB * QQ * TT];
__device__ float g_Ssp[KSPLIT * BB * QQ];
__device__ float g_Ssg[KSPLIT * BB * QQ];
__device__ float g_Sy[KSPLIT * BB * TT];

// ---------------- helpers ----------------
__device__ __forceinline__ uint32_t smem_u32(const void* p) {
    uint32_t a;
    asm("{ .reg .u64 t; cvta.to.shared.u64 t, %1; cvt.u32.u64 %0, t; }"
        : "=r"(a) : "l"(p));
    return a;
}
// softplus + sigmoid with 2 MUFU: tanh + lg2
__device__ __forceinline__ void act(float v, float& sp, float& sg) {
    float h;
    asm("tanh.approx.f32 %0, %1;" : "=f"(h) : "f"(0.5f * v));
    float sgn = fmaf(-0.5f, h, 0.5f);
    sg = fmaf(0.5f, h, 0.5f);
    sgn = fmaxf(sgn, 1e-30f);
    float lg;
    asm("lg2.approx.f32 %0, %1;" : "=f"(lg) : "f"(sgn));
    sp = -0.6931471805599453f * lg;
}
__device__ __forceinline__ float redWarp(float v) {
#pragma unroll
    for (int o = 16; o; o >>= 1) v += __shfl_xor_sync(0xFFFFFFFFu, v, o);
    return v;
}
#define LDSM4(r, addr)                                                        \
    asm volatile("ldmatrix.sync.aligned.m8n8.x4.shared.b16 {%0,%1,%2,%3}, [%4];" \
                 : "=r"((r)[0]), "=r"((r)[1]), "=r"((r)[2]), "=r"((r)[3])     \
                 : "r"(addr))
#define BAR_SYNC(id)   asm volatile("bar.sync %0, %1;" :: "r"(id), "r"(NTHREADS) : "memory")
#define BAR_ARRIVE(id) asm volatile("bar.arrive %0, %1;" :: "r"(id), "r"(NTHREADS) : "memory")
#define MEMBAR_CTA()   asm volatile("membar.cta;" ::: "memory")

// ---------------- main: activations + split-K HMMA GEMMs ----------------
__global__ void __launch_bounds__(NTHREADS, 1)
matcher_main(const float* __restrict__ m, const float* __restrict__ y) {
    extern __shared__ char smem[];
    uint32_t sb = smem_u32(smem);
    int tid = threadIdx.x;
    int wid = tid >> 5;
    int lane = tid & 31;
    int b = blockIdx.x / KSPLIT;
    int ks = blockIdx.x % KSPLIT;
    int nst = 28 + (ks < 4 ? 1 : 0);
    int s0 = 28 * ks + (ks < 4 ? ks : 4);
    int g0 = s0 * KC;

    // zero all buffers once (pad rows A[100:112), Y[50:64) must stay 0)
    {
        uint4 z = make_uint4(0u, 0u, 0u, 0u);
        for (int i = tid; i < SMEM_DYN / 16; i += NTHREADS)
            reinterpret_cast<uint4*>(smem)[i] = z;
    }
    __syncthreads();

    // roles: warps 0-6 = consumers (7 m16 strips, rows 0-111);
    //        warps 7-15 = fillers (9 warps)
    const bool isFill = (wid >= 7);
    const int fw = wid - 7;             // 0..8 for fillers

    if (isFill) {
        // ---------------- filler path ----------------
        float spA[12], sgA[12], syA[6];
#pragma unroll
        for (int j = 0; j < 12; ++j) { spA[j] = 0.0f; sgA[j] = 0.0f; }
#pragma unroll
        for (int j = 0; j < 6; ++j) syA[j] = 0.0f;

        const float* mBase = m + (size_t)b * QQ * GG + g0 + lane * 2;
        const float* yBase = y + (size_t)b * TT * GG + g0 + lane * 2;
        uint32_t stsOffBase = (uint32_t)(lane * 4);
        float2 vm[12], vy[6];

        auto loadUnit = [&](int it) {
            int gk = it * KC;
#pragma unroll
            for (int j = 0; j < 12; ++j) {
                int row = fw + 9 * j;
                if (row < QQ) vm[j] = *(const float2*)(mBase + (size_t)row * GG + gk);
            }
#pragma unroll
            for (int j = 0; j < 6; ++j) {
                int row = fw + 9 * j;
                if (row < TT) vy[j] = *(const float2*)(yBase + (size_t)row * GG + gk);
            }
        };
        auto storeUnit = [&](int buf) {
            char* stg = smem + buf * STAGE_BYTES;
#pragma unroll
            for (int j = 0; j < 12; ++j) {
                int row = fw + 9 * j;
                if (row < QQ) {
                    float sa, ga, sc, gc;
                    act(vm[j].x, sa, ga);
                    act(vm[j].y, sc, gc);
                    spA[j] += sa + sc;
                    sgA[j] += ga + gc;
                    uint32_t off = (uint32_t)(row * 128) +
                                   (stsOffBase ^ (uint32_t)((row & 7) << 4));
                    __nv_bfloat162 hm = __floats2bfloat162_rn(vm[j].x, vm[j].y);
                    __nv_bfloat162 hs = __floats2bfloat162_rn(ga, gc);
                    *(uint32_t*)(stg + OFF_AM + off) = *reinterpret_cast<uint32_t*>(&hm);
                    *(uint32_t*)(stg + OFF_AS + off) = *reinterpret_cast<uint32_t*>(&hs);
                }
            }
#pragma unroll
            for (int j = 0; j < 6; ++j) {
                int row = fw + 9 * j;
                if (row < TT) {
                    syA[j] += vy[j].x + vy[j].y;
                    uint32_t off = (uint32_t)(row * 128) +
                                   (stsOffBase ^ (uint32_t)((row & 7) << 4));
                    __nv_bfloat162 hv = __floats2bfloat162_rn(vy[j].x, vy[j].y);
                    *(uint32_t*)(stg + OFF_Y + off) = *reinterpret_cast<uint32_t*>(&hv);
                }
            }
        };

        loadUnit(0);
#pragma unroll 1
        for (int u = 0; u < nst; ++u) {
            int buf = u & (NBUF - 1);
            if (u >= NBUF) BAR_SYNC(5 + buf);   // wait FREE[buf]
            storeUnit(buf);
            MEMBAR_CTA();
            BAR_ARRIVE(1 + buf);                // signal FULL[buf]
            if (u + 1 < nst) loadUnit(u + 1);   // prefetch next (overlaps waits)
        }

        // row-sum reductions (one-time)
        int sl = ks * BB + b;
#pragma unroll
        for (int j = 0; j < 12; ++j) {
            int row = fw + 9 * j;
            if (row < QQ) {
                float s1 = redWarp(spA[j]);
                float s2 = redWarp(sgA[j]);
                if (lane == 0) {
                    g_Ssp[sl * QQ + row] = s1;
                    g_Ssg[sl * QQ + row] = s2;
                }
            }
        }
#pragma unroll
        for (int j = 0; j < 6; ++j) {
            int row = fw + 9 * j;
            if (row < TT) {
                float s3 = redWarp(syA[j]);
                if (lane == 0) g_Sy[sl * TT + row] = s3;
            }
        }
    } else {
        // ---------------- consumer path (wid 0..6 = strip) ----------------
        const int mt = wid;                 // strip rows mt*16 .. +16 (<=111)
        const int gq = lane >> 2;           // 0..7
        const int tig = lane & 3;           // 0..3
        float accM[7][4], accS[7][4];
#pragma unroll
        for (int nt = 0; nt < 7; ++nt)
#pragma unroll
            for (int i = 0; i < 4; ++i) { accM[nt][i] = 0.0f; accS[nt][i] = 0.0f; }

        uint32_t cmask = (uint32_t)((lane & 7) << 4);
        uint32_t rowAoff = (uint32_t)((mt * 16 + (lane & 15)) * 128);
        uint32_t chintA = (lane & 16) ? 16u : 0u;
        uint32_t chintB = (lane & 8) ? 16u : 0u;
        uint32_t rbB[4];
#pragma unroll
        for (int i = 0; i < 4; ++i) {
            uint32_t tB = (uint32_t)(16 * i + (lane & 7) + ((lane & 16) ? 8 : 0));
            rbB[i] = tB * 128;
        }

#pragma unroll 1
        for (int u = 0; u < nst; ++u) {
            int buf = u & (NBUF - 1);
            BAR_SYNC(1 + buf);              // wait FULL[buf]
            uint32_t base = sb + (uint32_t)(buf * STAGE_BYTES);
            uint32_t amb = base + OFF_AM + rowAoff;
            uint32_t asb = base + OFF_AS + rowAoff;
            uint32_t ybv = base + OFF_Y;
#pragma unroll
            for (int kc = 0; kc < 4; ++kc) {
                uint32_t cb16 = (uint32_t)(kc * 32);
                uint32_t ccA = (cb16 + chintA) ^ cmask;
                uint32_t ccB = (cb16 + chintB) ^ cmask;
                uint32_t am[4], as4[4], bb[4][4];
                LDSM4(am, amb + ccA);
                LDSM4(as4, asb + ccA);
#pragma unroll
                for (int i = 0; i < 4; ++i) LDSM4(bb[i], ybv + rbB[i] + ccB);
#pragma unroll
                for (int nt = 0; nt < 7; ++nt) {
                    uint32_t b0 = bb[nt >> 1][(nt & 1) * 2];
                    uint32_t b1 = bb[nt >> 1][(nt & 1) * 2 + 1];
                    asm volatile(
                        "mma.sync.aligned.m16n8k16.row.col.f32.bf16.bf16.f32 "
                        "{%0,%1,%2,%3}, {%4,%5,%6,%7}, {%8,%9}, {%0,%1,%2,%3};"
                        : "+f"(accM[nt][0]), "+f"(accM[nt][1]),
                          "+f"(accM[nt][2]), "+f"(accM[nt][3])
                        : "r"(am[0]), "r"(am[1]), "r"(am[2]), "r"(am[3]),
                          "r"(b0), "r"(b1));
                    asm volatile(
                        "mma.sync.aligned.m16n8k16.row.col.f32.bf16.bf16.f32 "
                        "{%0,%1,%2,%3}, {%4,%5,%6,%7}, {%8,%9}, {%0,%1,%2,%3};"
                        : "+f"(accS[nt][0]), "+f"(accS[nt][1]),
                          "+f"(accS[nt][2]), "+f"(accS[nt][3])
                        : "r"(as4[0]), "r"(as4[1]), "r"(as4[2]), "r"(as4[3]),
                          "r"(b0), "r"(b1));
                }
            }
            BAR_ARRIVE(5 + buf);            // signal FREE[buf]
        }

        // D slice stores (unique writer per entry, no atomics)
        int sl = ks * BB + b;
        int rl = mt * 16 + gq;
        int rh = rl + 8;
        size_t sbase = (size_t)sl * QQ * TT;
#pragma unroll
        for (int nt = 0; nt < 7; ++nt) {
            int ca = nt * 8 + tig * 2;
            int cb2 = ca + 1;
            if (rl < QQ) {
                if (ca < TT) {
                    g_Dm[sbase + rl * TT + ca] = accM[nt][0];
                    g_Ds[sbase + rl * TT + ca] = accS[nt][0];
                }
                if (cb2 < TT) {
                    g_Dm[sbase + rl * TT + cb2] = accM[nt][1];
                    g_Ds[sbase + rl * TT + cb2] = accS[nt][1];
                }
            }
            if (rh < QQ) {
                if (ca < TT) {
                    g_Dm[sbase + rh * TT + ca] = accM[nt][2];
                    g_Ds[sbase + rh * TT + ca] = accS[nt][2];
                }
                if (cb2 < TT) {
                    g_Dm[sbase + rh * TT + cb2] = accM[nt][3];
                    g_Ds[sbase + rh * TT + cb2] = accS[nt][3];
                }
            }
        }
    }
}

// ---------------- epilogue: one warp per (b,q) ----------------
__global__ void __launch_bounds__(128, 8)
matcher_epi(const float* __restrict__ cl,
            const int* __restrict__ lab32,
            float* __restrict__ out) {
    int warp = (blockIdx.x * blockDim.x + threadIdx.x) >> 5;
    int lane = threadIdx.x & 31;
    if (warp >= BB * QQ) return;
    int b = warp / QQ;
    int q = warp - b * QQ;

    int i64;
    {
        int ok = 1;
#pragma unroll
        for (int k = 0; k < 8; ++k) {
            int lo = lab32[2 * k], hi = lab32[2 * k + 1];
            if (hi != 0 || lo < 0 || lo >= LL) { ok = 0; break; }
        }
        i64 = ok;
    }

    const float* c = cl + (size_t)(b * QQ + q) * LL;
    float v = (lane < LL) ? c[lane] : -1e30f;
    float mx = v;
#pragma unroll
    for (int o = 16; o; o >>= 1) mx = fmaxf(mx, __shfl_xor_sync(0xFFFFFFFFu, mx, o));
    float e = (lane < LL) ? __expf(v - mx) : 0.0f;
    float s = e;
#pragma unroll
    for (int o = 16; o; o >>= 1) s += __shfl_xor_sync(0xFFFFFFFFu, s, o);
    float pl = e / s;

    float ssp = 0.0f, ssg = 0.0f;
#pragma unroll
    for (int ks = 0; ks < KSPLIT; ++ks) {
        int sl = ks * BB + b;
        ssp += g_Ssp[sl * QQ + q];
        ssg += g_Ssg[sl * QQ + q];
    }

    const float invG = 1.0f / (float)GG;
    size_t rowoff = (size_t)(b * QQ + q) * TT;

#pragma unroll
    for (int half = 0; half < 2; ++half) {
        int t = lane + half * 32;
        if (t < TT) {
            float dm = 0.0f, ds = 0.0f, sy = 0.0f;
#pragma unroll
            for (int ks = 0; ks < KSPLIT; ++ks) {
                int sl = ks * BB + b;
                size_t off = (size_t)sl * QQ * TT + q * TT + t;
                dm += g_Dm[off];
                ds += g_Ds[off];
                sy += g_Sy[sl * TT + t];
            }
            int idx = b * TT + t;
            int lbl = i64 ? lab32[2 * idx] : lab32[idx];
            float p = __shfl_sync(0xFFFFFFFFu, pl, lbl);
            float dice = 1.0f - (2.0f * ds + 1.0f) / (ssg + sy + 1.0f);
            out[rowoff + t] = (ssp - dm) * invG - p + dice;
        } else {
            __shfl_sync(0xFFFFFFFFu, pl, 0);
        }
    }
}

// ---------------- launch ----------------
extern "C" void kernel_launch(void* const* d_in, const int* in_sizes, int n_in,
                              void* d_out, int out_size) {
    (void)in_sizes; (void)n_in; (void)out_size;
    const float* m = (const float*)d_in[0];
    const float* cl = (const float*)d_in[1];
    const float* y = (const float*)d_in[2];
    const int* lab = (const int*)d_in[3];
    float* out = (float*)d_out;

    cudaFuncSetAttribute(matcher_main,
                         cudaFuncAttributeMaxDynamicSharedMemorySize, SMEM_DYN);

    matcher_main<<<BB * KSPLIT, NTHREADS, SMEM_DYN>>>(m, y);
    matcher_epi<<<(BB * QQ + 3) / 4, 128>>>(cl, lab, out);
}